// round 15
// baseline (speedup 1.0000x reference)
#include <cuda_runtime.h>
#include <cuda_bf16.h>
#include <mma.h>
#include <cstdint>

using namespace nvcuda;

#define NN 100000
#define EE 1600000
#define FF 64
#define KK 6
#define NBLK_SCAN 98   /* ceil(NN/1024) */

// ---------------- scratch (static device globals; allocation-free) ----------
__device__ int   g_deg[NN];
__device__ float g_dinv[NN];
__device__ int   g_cnt[NN];
__device__ int   g_cursor[NN];
__device__ int   g_rowptr[NN + 1];
__device__ int   g_bsum[NBLK_SCAN];
__device__ int   g_boff[NBLK_SCAN];
__device__ int   g_srcs[EE];
__device__ float g_wts[EE];
__device__ float g_tx[5][(size_t)NN * FF];   // Tx1..Tx5 (fp32)

// ---------------- CSR build (EXACT R1/R11) -----------------------------------
__global__ void zero_kernel() {
    int i = blockIdx.x * blockDim.x + threadIdx.x;
    if (i < NN) { g_deg[i] = 0; g_cnt[i] = 0; g_cursor[i] = 0; }
}

__global__ void hist_kernel(const int* __restrict__ ei) {
    int e = blockIdx.x * blockDim.x + threadIdx.x;
    if (e < EE) {
        atomicAdd(&g_deg[ei[e]], 1);
        atomicAdd(&g_cnt[ei[EE + e]], 1);
    }
}

__global__ void dinv_kernel() {
    int i = blockIdx.x * blockDim.x + threadIdx.x;
    if (i < NN) {
        int d = g_deg[i];
        g_dinv[i] = (d > 0) ? rsqrtf((float)d) : 0.0f;
    }
}

__global__ void scanA_kernel() {
    __shared__ int sh[1024];
    int t   = threadIdx.x;
    int idx = blockIdx.x * 1024 + t;
    int v   = (idx < NN) ? g_cnt[idx] : 0;
    sh[t] = v;
    __syncthreads();
    for (int off = 1; off < 1024; off <<= 1) {
        int tv = (t >= off) ? sh[t - off] : 0;
        __syncthreads();
        sh[t] += tv;
        __syncthreads();
    }
    if (idx < NN) g_rowptr[idx] = sh[t] - v;
    if (t == 1023) g_bsum[blockIdx.x] = sh[1023];
}

__global__ void scanB_kernel() {
    if (threadIdx.x == 0) {
        int acc = 0;
        for (int i = 0; i < NBLK_SCAN; i++) { g_boff[i] = acc; acc += g_bsum[i]; }
        g_rowptr[NN] = acc;
    }
}

__global__ void scanC_kernel() {
    int idx = blockIdx.x * blockDim.x + threadIdx.x;
    if (idx < NN) g_rowptr[idx] += g_boff[idx >> 10];
}

__global__ void scatter_kernel(const int* __restrict__ ei) {
    int e = blockIdx.x * blockDim.x + threadIdx.x;
    if (e < EE) {
        int r = ei[e];
        int c = ei[EE + e];
        int pos = g_rowptr[c] + atomicAdd(&g_cursor[c], 1);
        g_srcs[pos] = r;
        g_wts[pos]  = -(g_dinv[r] * g_dinv[c]);
    }
}

// ---------------- propagation (EXACT R11) ------------------------------------
__global__ void prop_kernel(const float* __restrict__ x,
                            int h_idx, int sub_idx, float alpha, int out_idx) {
    int gw   = (blockIdx.x * blockDim.x + threadIdx.x) >> 5;
    int lane = threadIdx.x & 31;
    if (gw >= NN) return;

    const float* h = (h_idx < 0) ? x : g_tx[h_idx];
    int s = g_rowptr[gw];
    int e = g_rowptr[gw + 1];

    float ax = 0.0f, ay = 0.0f;
    for (int i = s; i < e; i++) {
        int   sr = g_srcs[i];
        float wv = g_wts[i];
        float2 hv = ((const float2*)(h + (size_t)sr * FF))[lane];
        ax = fmaf(wv, hv.x, ax);
        ay = fmaf(wv, hv.y, ay);
    }
    float rx = alpha * ax, ry = alpha * ay;
    if (sub_idx > -2) {
        const float* sb = (sub_idx < 0) ? x : g_tx[sub_idx];
        float2 sv = ((const float2*)(sb + (size_t)gw * FF))[lane];
        rx -= sv.x; ry -= sv.y;
    }
    float2 r; r.x = rx; r.y = ry;
    ((float2*)(g_tx[out_idx] + (size_t)gw * FF))[lane] = r;
}

// ================= wmma bf16 GEMM, M-tile = 128 ==============================
// CTA = 256 threads / 8 warps; tile = 128 nodes x 64 outs. Each warp: fixed
// 16-wide n-column, four 16x16 m-subtiles (4 fp32 acc fragments). W restaged
// once per CTA per k -> 4x less W L2 traffic than the 32-row tile.
// 2-term bf16 split (hh + hl + lh) unchanged.

#define APAD 72   /* bf16 row stride for A/W smem tiles (bank-conflict pad) */
#define TM   128  /* nodes per CTA tile */

// dynamic smem offsets (bytes)
#define SO_AHI  0
#define SO_ALO  (TM * APAD * 2)                 /* 18432 */
#define SO_WHI  (2 * TM * APAD * 2)             /* 36864 */
#define SO_WLO  (2 * TM * APAD * 2 + 64 * APAD * 2)   /* 46080 */
#define SO_TOT  (2 * TM * APAD * 2 + 2 * 64 * APAD * 2) /* 55296 */
/* sOut (128*64 f32 = 32768 B) aliases the A region after the last barrier */

__device__ __forceinline__ void wm_split(float v, __nv_bfloat16& h, __nv_bfloat16& l) {
    h = __float2bfloat16(v);
    l = __float2bfloat16(v - __bfloat162float(h));
}

__global__ __launch_bounds__(256) void wmma_gemm_kernel(const float* __restrict__ x,
                                                        const float* __restrict__ W,
                                                        const float* __restrict__ b,
                                                        float* __restrict__ out) {
    extern __shared__ char smem[];
    __nv_bfloat16* sAhi = (__nv_bfloat16*)(smem + SO_AHI);
    __nv_bfloat16* sAlo = (__nv_bfloat16*)(smem + SO_ALO);
    __nv_bfloat16* sWhi = (__nv_bfloat16*)(smem + SO_WHI);
    __nv_bfloat16* sWlo = (__nv_bfloat16*)(smem + SO_WLO);
    float*         sOut = (float*)smem;   // aliases A region (epilogue only)

    int tid  = threadIdx.x;
    int warp = tid >> 5;
    int m0   = blockIdx.x * TM;

    int w_mb = (warp >> 2) * 16;    // 0 or 16: m-subtile base within 32-row group
    int w_n  = (warp & 3) * 16;     // 0,16,32,48: out-feature subtile col

    wmma::fragment<wmma::accumulator, 16, 16, 16, float> acc[4];
#pragma unroll
    for (int i = 0; i < 4; i++) wmma::fill_fragment(acc[i], 0.0f);

#pragma unroll 1
    for (int k = 0; k < KK; k++) {
        // ---- stage A tile: 128 nodes x 64 features, fp32 -> bf16 hi/lo ----
        const float* hb = (k == 0) ? x : g_tx[k - 1];
        for (int idx = tid; idx < TM * 16; idx += 256) {
            int r = idx >> 4, c4 = idx & 15;
            int node = m0 + r;
            float4 v = (node < NN) ? __ldg((const float4*)(hb + (size_t)node * FF) + c4)
                                   : make_float4(0.f, 0.f, 0.f, 0.f);
            __nv_bfloat16 h0, l0, h1, l1, h2, l2, h3, l3;
            wm_split(v.x, h0, l0); wm_split(v.y, h1, l1);
            wm_split(v.z, h2, l2); wm_split(v.w, h3, l3);
            int o = r * APAD + c4 * 4;
            sAhi[o] = h0; sAhi[o+1] = h1; sAhi[o+2] = h2; sAhi[o+3] = h3;
            sAlo[o] = l0; sAlo[o+1] = l1; sAlo[o+2] = l2; sAlo[o+3] = l3;
        }
        // ---- stage W_k: 64x64 row-major (in x out) -> bf16 hi/lo ----
        for (int idx = tid; idx < 64 * 16; idx += 256) {
            int r = idx >> 4, c4 = idx & 15;
            float4 v = __ldg((const float4*)(W + k * FF * FF + r * FF) + c4);
            __nv_bfloat16 h0, l0, h1, l1, h2, l2, h3, l3;
            wm_split(v.x, h0, l0); wm_split(v.y, h1, l1);
            wm_split(v.z, h2, l2); wm_split(v.w, h3, l3);
            int o = r * APAD + c4 * 4;
            sWhi[o] = h0; sWhi[o+1] = h1; sWhi[o+2] = h2; sWhi[o+3] = h3;
            sWlo[o] = l0; sWlo[o+1] = l1; sWlo[o+2] = l2; sWlo[o+3] = l3;
        }
        __syncthreads();

        // ---- 4 k-chunks x (1 W-pair load + 4 m-subtiles x 3 products) ----
#pragma unroll
        for (int kk = 0; kk < 4; kk++) {
            wmma::fragment<wmma::matrix_b, 16, 16, 16, __nv_bfloat16, wmma::row_major> b_hi, b_lo;
            wmma::load_matrix_sync(b_hi, &sWhi[(kk * 16) * APAD + w_n], APAD);
            wmma::load_matrix_sync(b_lo, &sWlo[(kk * 16) * APAD + w_n], APAD);
#pragma unroll
            for (int i = 0; i < 4; i++) {
                int mrow = w_mb + 32 * i;
                wmma::fragment<wmma::matrix_a, 16, 16, 16, __nv_bfloat16, wmma::row_major> a_hi, a_lo;
                wmma::load_matrix_sync(a_hi, &sAhi[mrow * APAD + kk * 16], APAD);
                wmma::load_matrix_sync(a_lo, &sAlo[mrow * APAD + kk * 16], APAD);
                wmma::mma_sync(acc[i], a_hi, b_hi, acc[i]);
                wmma::mma_sync(acc[i], a_hi, b_lo, acc[i]);
                wmma::mma_sync(acc[i], a_lo, b_hi, acc[i]);
            }
        }
        __syncthreads();   // before restaging smem for next k (and before sOut alias)
    }

    // ---- epilogue: frags -> sOut (aliases A), bias + relu, float4 stores ----
#pragma unroll
    for (int i = 0; i < 4; i++)
        wmma::store_matrix_sync(&sOut[(w_mb + 32 * i) * 64 + w_n], acc[i], 64,
                                wmma::mem_row_major);
    __syncthreads();

    for (int idx = tid; idx < TM * 16; idx += 256) {
        int r = idx >> 4, c4 = idx & 15;
        int node = m0 + r;
        if (node >= NN) break;
        float4 v = ((const float4*)(sOut + r * 64))[c4];
        v.x = fmaxf(v.x + __ldg(b + c4 * 4 + 0), 0.0f);
        v.y = fmaxf(v.y + __ldg(b + c4 * 4 + 1), 0.0f);
        v.z = fmaxf(v.z + __ldg(b + c4 * 4 + 2), 0.0f);
        v.w = fmaxf(v.w + __ldg(b + c4 * 4 + 3), 0.0f);
        ((float4*)(out + (size_t)node * FF))[c4] = v;
    }
}

// ---------------- launch ----------------------------------------------------
extern "C" void kernel_launch(void* const* d_in, const int* in_sizes, int n_in,
                              void* d_out, int out_size) {
    const float* x  = (const float*)d_in[0];   // [N, 64]
    const int*   ei = (const int*)d_in[1];     // [2, E]: src row then dst row
    const float* W  = (const float*)d_in[2];   // [6, 64, 64]
    const float* b  = (const float*)d_in[3];   // [64]
    float* out = (float*)d_out;                // [N, 64]

    cudaFuncSetAttribute(wmma_gemm_kernel,
                         cudaFuncAttributeMaxDynamicSharedMemorySize, SO_TOT);

    const int TB = 256;
    zero_kernel   <<<(NN + TB - 1) / TB, TB>>>();
    hist_kernel   <<<(EE + TB - 1) / TB, TB>>>(ei);
    dinv_kernel   <<<(NN + TB - 1) / TB, TB>>>();
    scanA_kernel  <<<NBLK_SCAN, 1024>>>();
    scanB_kernel  <<<1, 32>>>();
    scanC_kernel  <<<(NN + TB - 1) / TB, TB>>>();
    scatter_kernel<<<(EE + TB - 1) / TB, TB>>>(ei);

    int prop_blocks = (NN * 32 + TB - 1) / TB;   // warp per node
    prop_kernel<<<prop_blocks, TB>>>(x, -1, -2, 1.0f, 0);  // Tx1 = L x
    prop_kernel<<<prop_blocks, TB>>>(x,  0, -1, 2.0f, 1);  // Tx2 = 2 L Tx1 - x
    prop_kernel<<<prop_blocks, TB>>>(x,  1,  0, 2.0f, 2);  // Tx3
    prop_kernel<<<prop_blocks, TB>>>(x,  2,  1, 2.0f, 3);  // Tx4
    prop_kernel<<<prop_blocks, TB>>>(x,  3,  2, 2.0f, 4);  // Tx5

    wmma_gemm_kernel<<<(NN + TM - 1) / TM, TB, SO_TOT>>>(x, W, b, out);  // 782 CTAs
}

// round 17
// speedup vs baseline: 1.3132x; 1.3132x over previous
#include <cuda_runtime.h>
#include <cuda_bf16.h>
#include <mma.h>
#include <cstdint>

using namespace nvcuda;

#define NN 100000
#define EE 1600000
#define FF 64
#define KK 6
#define NBLK_SCAN 98   /* ceil(NN/1024) */

// ---------------- scratch (static device globals; allocation-free) ----------
__device__ int   g_deg[NN];
__device__ float g_dinv[NN];
__device__ int   g_cnt[NN];
__device__ int   g_cursor[NN];
__device__ int   g_rowptr[NN + 1];
__device__ int   g_bsum[NBLK_SCAN];
__device__ int   g_boff[NBLK_SCAN];
__device__ int   g_srcs[EE];
__device__ float g_wts[EE];
__device__ float g_tx[5][(size_t)NN * FF];   // Tx1..Tx5 (fp32)

// ---------------- CSR build (EXACT R11 except scanB) -------------------------
__global__ void zero_kernel() {
    int i = blockIdx.x * blockDim.x + threadIdx.x;
    if (i < NN) { g_deg[i] = 0; g_cnt[i] = 0; g_cursor[i] = 0; }
}

__global__ void hist_kernel(const int* __restrict__ ei) {
    int e = blockIdx.x * blockDim.x + threadIdx.x;
    if (e < EE) {
        atomicAdd(&g_deg[ei[e]], 1);
        atomicAdd(&g_cnt[ei[EE + e]], 1);
    }
}

__global__ void dinv_kernel() {
    int i = blockIdx.x * blockDim.x + threadIdx.x;
    if (i < NN) {
        int d = g_deg[i];
        g_dinv[i] = (d > 0) ? rsqrtf((float)d) : 0.0f;
    }
}

__global__ void scanA_kernel() {
    __shared__ int sh[1024];
    int t   = threadIdx.x;
    int idx = blockIdx.x * 1024 + t;
    int v   = (idx < NN) ? g_cnt[idx] : 0;
    sh[t] = v;
    __syncthreads();
    for (int off = 1; off < 1024; off <<= 1) {
        int tv = (t >= off) ? sh[t - off] : 0;
        __syncthreads();
        sh[t] += tv;
        __syncthreads();
    }
    if (idx < NN) g_rowptr[idx] = sh[t] - v;
    if (t == 1023) g_bsum[blockIdx.x] = sh[1023];
}

// Block-parallel scan of the 98 block sums (was: 1 thread x 98 dependent LDGs).
// 128 threads: one coalesced load round-trip + 7-step Hillis-Steele in smem.
__global__ void scanB_kernel() {
    __shared__ int sh[128];
    int t = threadIdx.x;
    int v = (t < NBLK_SCAN) ? g_bsum[t] : 0;
    sh[t] = v;
    __syncthreads();
#pragma unroll
    for (int off = 1; off < 128; off <<= 1) {
        int tv = (t >= off) ? sh[t - off] : 0;
        __syncthreads();
        sh[t] += tv;
        __syncthreads();
    }
    if (t < NBLK_SCAN) g_boff[t] = sh[t] - v;   // exclusive
    if (t == NBLK_SCAN - 1) g_rowptr[NN] = sh[t];   // total == EE
}

__global__ void scanC_kernel() {
    int idx = blockIdx.x * blockDim.x + threadIdx.x;
    if (idx < NN) g_rowptr[idx] += g_boff[idx >> 10];
}

__global__ void scatter_kernel(const int* __restrict__ ei) {
    int e = blockIdx.x * blockDim.x + threadIdx.x;
    if (e < EE) {
        int r = ei[e];
        int c = ei[EE + e];
        int pos = g_rowptr[c] + atomicAdd(&g_cursor[c], 1);
        g_srcs[pos] = r;
        g_wts[pos]  = -(g_dinv[r] * g_dinv[c]);
    }
}

// ---------------- propagation (EXACT R11) ------------------------------------
__global__ void prop_kernel(const float* __restrict__ x,
                            int h_idx, int sub_idx, float alpha, int out_idx) {
    int gw   = (blockIdx.x * blockDim.x + threadIdx.x) >> 5;
    int lane = threadIdx.x & 31;
    if (gw >= NN) return;

    const float* h = (h_idx < 0) ? x : g_tx[h_idx];
    int s = g_rowptr[gw];
    int e = g_rowptr[gw + 1];

    float ax = 0.0f, ay = 0.0f;
    for (int i = s; i < e; i++) {
        int   sr = g_srcs[i];
        float wv = g_wts[i];
        float2 hv = ((const float2*)(h + (size_t)sr * FF))[lane];
        ax = fmaf(wv, hv.x, ax);
        ay = fmaf(wv, hv.y, ay);
    }
    float rx = alpha * ax, ry = alpha * ay;
    if (sub_idx > -2) {
        const float* sb = (sub_idx < 0) ? x : g_tx[sub_idx];
        float2 sv = ((const float2*)(sb + (size_t)gw * FF))[lane];
        rx -= sv.x; ry -= sv.y;
    }
    float2 r; r.x = rx; r.y = ry;
    ((float2*)(g_tx[out_idx] + (size_t)gw * FF))[lane] = r;
}

// ================= wmma bf16 GEMM (EXACT R11) ===============================
// CTA = 256 threads / 8 warps; tile = 32 nodes x 64 outs (NN = 3125*32 exact).
// 2-term bf16 split (hh + hl + lh) for fp32-class accuracy on the HMMA pipe.

#define APAD 72   /* bf16 row stride for A/W smem tiles (bank-conflict pad) */

__device__ __forceinline__ void wm_split(float v, __nv_bfloat16& h, __nv_bfloat16& l) {
    h = __float2bfloat16(v);
    l = __float2bfloat16(v - __bfloat162float(h));
}

__global__ __launch_bounds__(256) void wmma_gemm_kernel(const float* __restrict__ x,
                                                        const float* __restrict__ W,
                                                        const float* __restrict__ b,
                                                        float* __restrict__ out) {
    __shared__ __nv_bfloat16 sAhi[32 * APAD];
    __shared__ __nv_bfloat16 sAlo[32 * APAD];
    __shared__ __nv_bfloat16 sWhi[64 * APAD];
    __shared__ __nv_bfloat16 sWlo[64 * APAD];
    __shared__ float         sOut[32 * 64];

    int tid  = threadIdx.x;
    int warp = tid >> 5;
    int m0   = blockIdx.x * 32;

    int w_m = (warp >> 2) * 16;     // 0 or 16: node-subtile row
    int w_n = (warp & 3) * 16;      // 0,16,32,48: out-feature subtile col

    wmma::fragment<wmma::accumulator, 16, 16, 16, float> acc;
    wmma::fill_fragment(acc, 0.0f);

#pragma unroll 1
    for (int k = 0; k < KK; k++) {
        // ---- stage A tile: 32 nodes x 64 features, fp32 -> bf16 hi/lo ----
        const float* hb = (k == 0) ? x : g_tx[k - 1];
        for (int idx = tid; idx < 32 * 16; idx += 256) {
            int r = idx >> 4, c4 = idx & 15;
            float4 v = __ldg((const float4*)(hb + (size_t)(m0 + r) * FF) + c4);
            __nv_bfloat16 h0, l0, h1, l1, h2, l2, h3, l3;
            wm_split(v.x, h0, l0); wm_split(v.y, h1, l1);
            wm_split(v.z, h2, l2); wm_split(v.w, h3, l3);
            int o = r * APAD + c4 * 4;
            sAhi[o] = h0; sAhi[o+1] = h1; sAhi[o+2] = h2; sAhi[o+3] = h3;
            sAlo[o] = l0; sAlo[o+1] = l1; sAlo[o+2] = l2; sAlo[o+3] = l3;
        }
        // ---- stage W_k: 64x64 row-major (in x out) -> bf16 hi/lo ----
        for (int idx = tid; idx < 64 * 16; idx += 256) {
            int r = idx >> 4, c4 = idx & 15;
            float4 v = __ldg((const float4*)(W + k * FF * FF + r * FF) + c4);
            __nv_bfloat16 h0, l0, h1, l1, h2, l2, h3, l3;
            wm_split(v.x, h0, l0); wm_split(v.y, h1, l1);
            wm_split(v.z, h2, l2); wm_split(v.w, h3, l3);
            int o = r * APAD + c4 * 4;
            sWhi[o] = h0; sWhi[o+1] = h1; sWhi[o+2] = h2; sWhi[o+3] = h3;
            sWlo[o] = l0; sWlo[o+1] = l1; sWlo[o+2] = l2; sWlo[o+3] = l3;
        }
        __syncthreads();

        // ---- 4 k-chunks x 3 split products ----
#pragma unroll
        for (int kk = 0; kk < 4; kk++) {
            wmma::fragment<wmma::matrix_a, 16, 16, 16, __nv_bfloat16, wmma::row_major> a_hi, a_lo;
            wmma::fragment<wmma::matrix_b, 16, 16, 16, __nv_bfloat16, wmma::row_major> b_hi, b_lo;
            wmma::load_matrix_sync(a_hi, &sAhi[w_m * APAD + kk * 16], APAD);
            wmma::load_matrix_sync(a_lo, &sAlo[w_m * APAD + kk * 16], APAD);
            wmma::load_matrix_sync(b_hi, &sWhi[(kk * 16) * APAD + w_n], APAD);
            wmma::load_matrix_sync(b_lo, &sWlo[(kk * 16) * APAD + w_n], APAD);
            wmma::mma_sync(acc, a_hi, b_hi, acc);
            wmma::mma_sync(acc, a_hi, b_lo, acc);
            wmma::mma_sync(acc, a_lo, b_hi, acc);
        }
        __syncthreads();   // before restaging smem for next k
    }

    // ---- epilogue: frag -> smem, bias + relu, float4 stores ----
    wmma::store_matrix_sync(&sOut[w_m * 64 + w_n], acc, 64, wmma::mem_row_major);
    __syncthreads();

    for (int idx = tid; idx < 32 * 16; idx += 256) {
        int r = idx >> 4, c4 = idx & 15;
        float4 v = ((const float4*)(sOut + r * 64))[c4];
        v.x = fmaxf(v.x + __ldg(b + c4 * 4 + 0), 0.0f);
        v.y = fmaxf(v.y + __ldg(b + c4 * 4 + 1), 0.0f);
        v.z = fmaxf(v.z + __ldg(b + c4 * 4 + 2), 0.0f);
        v.w = fmaxf(v.w + __ldg(b + c4 * 4 + 3), 0.0f);
        ((float4*)(out + (size_t)(m0 + r) * FF))[c4] = v;
    }
}

// ---------------- launch ----------------------------------------------------
extern "C" void kernel_launch(void* const* d_in, const int* in_sizes, int n_in,
                              void* d_out, int out_size) {
    const float* x  = (const float*)d_in[0];   // [N, 64]
    const int*   ei = (const int*)d_in[1];     // [2, E]: src row then dst row
    const float* W  = (const float*)d_in[2];   // [6, 64, 64]
    const float* b  = (const float*)d_in[3];   // [64]
    float* out = (float*)d_out;                // [N, 64]

    const int TB = 256;
    zero_kernel   <<<(NN + TB - 1) / TB, TB>>>();
    hist_kernel   <<<(EE + TB - 1) / TB, TB>>>(ei);
    dinv_kernel   <<<(NN + TB - 1) / TB, TB>>>();
    scanA_kernel  <<<NBLK_SCAN, 1024>>>();
    scanB_kernel  <<<1, 128>>>();
    scanC_kernel  <<<(NN + TB - 1) / TB, TB>>>();
    scatter_kernel<<<(EE + TB - 1) / TB, TB>>>(ei);

    int prop_blocks = (NN * 32 + TB - 1) / TB;   // warp per node
    prop_kernel<<<prop_blocks, TB>>>(x, -1, -2, 1.0f, 0);  // Tx1 = L x
    prop_kernel<<<prop_blocks, TB>>>(x,  0, -1, 2.0f, 1);  // Tx2 = 2 L Tx1 - x
    prop_kernel<<<prop_blocks, TB>>>(x,  1,  0, 2.0f, 2);  // Tx3
    prop_kernel<<<prop_blocks, TB>>>(x,  2,  1, 2.0f, 3);  // Tx4
    prop_kernel<<<prop_blocks, TB>>>(x,  3,  2, 2.0f, 4);  // Tx5

    wmma_gemm_kernel<<<NN / 32, TB>>>(x, W, b, out);   // 3125 CTAs, exact
}